// round 1
// baseline (speedup 1.0000x reference)
#include <cuda_runtime.h>
#include <cuda_bf16.h>
#include <cstdint>

// B=256 batches, N=256. Output [B, N, 8] fp32.
// slots: 0 = ones, 1 = diag(P), 2 = diag(P^2), 3 = diag(P^3), 4 = diag(P^4),
//        5 = diag(P^2 P^3), 6 = diag(P^3 P^3), 7 = diag(P^3 P^4)

#define BDIM 256
#define NN   256
#define MATS (256LL * 256 * 256)

__device__ float g_P [MATS];
__device__ float g_P2[MATS];
__device__ float g_P3[MATS];
__device__ float g_P4[MATS];

// ---------------------------------------------------------------------------
// Kernel 1: threshold + row normalize. One block per (b, row). 256 threads.
// Also writes out slot 0 (ones) and slot 1 (diag(P)).
// ---------------------------------------------------------------------------
__global__ void __launch_bounds__(256) prep_kernel(const float* __restrict__ A,
                                                   float* __restrict__ P,
                                                   float* __restrict__ out)
{
    int row = blockIdx.x;            // b*256 + n
    int n   = row & 255;
    int t   = threadIdx.x;

    const float* arow = A + (size_t)row * NN;
    float v = arow[t];
    float a = (v > 0.3f) ? v : 0.0f;

    // block reduce sum of a
    float s = a;
    #pragma unroll
    for (int o = 16; o; o >>= 1) s += __shfl_xor_sync(0xffffffffu, s, o);
    __shared__ float ws[8];
    if ((t & 31) == 0) ws[t >> 5] = s;
    __syncthreads();
    float deg = ws[0] + ws[1] + ws[2] + ws[3] + ws[4] + ws[5] + ws[6] + ws[7];

    float dinv = (deg > 0.0f) ? (1.0f / deg) : 0.0f;
    float p = a * dinv;
    P[(size_t)row * NN + t] = p;

    if (t == n) out[(size_t)row * 8 + 1] = p;
    if (t == 0) out[(size_t)row * 8 + 0] = 1.0f;
}

// ---------------------------------------------------------------------------
// Kernel 2: batched 256x256x256 fp32 SGEMM, C = A*B, 128x128 tiles,
// 256 threads, 8x8 microtile, double-buffered smem.
// blockIdx.z selects between two (A,B,C,slot) problem descriptors so P3 and
// P4 (both depending only on P/P2) run in a single launch.
// Diagonal of C is written to out[..., slot] in the epilogue.
// ---------------------------------------------------------------------------
__global__ void __launch_bounds__(256, 2)
gemm_kernel(const float* __restrict__ Aall0, const float* __restrict__ Ball0,
            float* __restrict__ Call0, int slot0,
            const float* __restrict__ Aall1, const float* __restrict__ Ball1,
            float* __restrict__ Call1, int slot1,
            float* __restrict__ out)
{
    const float* Aall = blockIdx.z ? Aall1 : Aall0;
    const float* Ball = blockIdx.z ? Ball1 : Ball0;
    float*       Call = blockIdx.z ? Call1 : Call0;
    int          slot = blockIdx.z ? slot1 : slot0;

    int b = blockIdx.y;
    size_t base = (size_t)b << 16;   // b * 256 * 256
    const float* A = Aall + base;
    const float* B = Ball + base;
    float*       C = Call + base;

    int tileM = (blockIdx.x >> 1) << 7;   // 0 or 128
    int tileN = (blockIdx.x & 1) << 7;

    __shared__ float sA[2][16][128];   // transposed: sA[k][m]
    __shared__ float sB[2][16][128];   // sB[k][n]

    int tid = threadIdx.x;
    int tx = tid & 15;       // 16 thread cols
    int ty = tid >> 4;       // 16 thread rows

    // A tile (128 rows x 16 cols) as 512 float4: f -> r=f>>2, c=(f&3)*4
    int ar0 = tid >> 2;             // 0..63 (second at +64)
    int ac  = (tid & 3) << 2;       // 0,4,8,12
    // B tile (16 rows x 128 cols) as 512 float4: f -> r=f>>5, c=(f&31)*4
    int br0 = tid >> 5;             // 0..7 (second at +8)
    int bc  = (tid & 31) << 2;      // 0..124

    float acc[8][8];
    #pragma unroll
    for (int i = 0; i < 8; i++)
        #pragma unroll
        for (int j = 0; j < 8; j++) acc[i][j] = 0.0f;

    float4 a0, a1, b0, b1;

    // prefetch k-tile 0
    a0 = *(const float4*)&A[(size_t)(tileM + ar0)      * NN + 0 + ac];
    a1 = *(const float4*)&A[(size_t)(tileM + ar0 + 64) * NN + 0 + ac];
    b0 = *(const float4*)&B[(size_t)(0 + br0)     * NN + tileN + bc];
    b1 = *(const float4*)&B[(size_t)(0 + br0 + 8) * NN + tileN + bc];

    sA[0][ac + 0][ar0] = a0.x; sA[0][ac + 1][ar0] = a0.y;
    sA[0][ac + 2][ar0] = a0.z; sA[0][ac + 3][ar0] = a0.w;
    sA[0][ac + 0][ar0 + 64] = a1.x; sA[0][ac + 1][ar0 + 64] = a1.y;
    sA[0][ac + 2][ar0 + 64] = a1.z; sA[0][ac + 3][ar0 + 64] = a1.w;
    *(float4*)&sB[0][br0][bc]     = b0;
    *(float4*)&sB[0][br0 + 8][bc] = b1;
    __syncthreads();

    #pragma unroll 1
    for (int kt = 0; kt < 16; kt++) {
        int cur = kt & 1;
        if (kt < 15) {
            int k0 = (kt + 1) << 4;
            a0 = *(const float4*)&A[(size_t)(tileM + ar0)      * NN + k0 + ac];
            a1 = *(const float4*)&A[(size_t)(tileM + ar0 + 64) * NN + k0 + ac];
            b0 = *(const float4*)&B[(size_t)(k0 + br0)     * NN + tileN + bc];
            b1 = *(const float4*)&B[(size_t)(k0 + br0 + 8) * NN + tileN + bc];
        }

        #pragma unroll
        for (int kk = 0; kk < 16; kk++) {
            float ra[8], rb[8];
            *(float4*)&ra[0] = *(const float4*)&sA[cur][kk][ty * 8];
            *(float4*)&ra[4] = *(const float4*)&sA[cur][kk][ty * 8 + 4];
            *(float4*)&rb[0] = *(const float4*)&sB[cur][kk][tx * 8];
            *(float4*)&rb[4] = *(const float4*)&sB[cur][kk][tx * 8 + 4];
            #pragma unroll
            for (int i = 0; i < 8; i++)
                #pragma unroll
                for (int j = 0; j < 8; j++)
                    acc[i][j] = fmaf(ra[i], rb[j], acc[i][j]);
        }

        if (kt < 15) {
            int nxt = cur ^ 1;
            sA[nxt][ac + 0][ar0] = a0.x; sA[nxt][ac + 1][ar0] = a0.y;
            sA[nxt][ac + 2][ar0] = a0.z; sA[nxt][ac + 3][ar0] = a0.w;
            sA[nxt][ac + 0][ar0 + 64] = a1.x; sA[nxt][ac + 1][ar0 + 64] = a1.y;
            sA[nxt][ac + 2][ar0 + 64] = a1.z; sA[nxt][ac + 3][ar0 + 64] = a1.w;
            *(float4*)&sB[nxt][br0][bc]     = b0;
            *(float4*)&sB[nxt][br0 + 8][bc] = b1;
        }
        __syncthreads();
    }

    // epilogue: store C, extract diagonal into out slot
    #pragma unroll
    for (int i = 0; i < 8; i++) {
        int r = tileM + ty * 8 + i;
        float4 v0 = make_float4(acc[i][0], acc[i][1], acc[i][2], acc[i][3]);
        float4 v1 = make_float4(acc[i][4], acc[i][5], acc[i][6], acc[i][7]);
        *(float4*)&C[(size_t)r * NN + tileN + tx * 8]     = v0;
        *(float4*)&C[(size_t)r * NN + tileN + tx * 8 + 4] = v1;
    }
    if (tileM == tileN && tx == ty) {
        #pragma unroll
        for (int i = 0; i < 8; i++) {
            int r = tileM + ty * 8 + i;
            out[((size_t)b * NN + r) * 8 + slot] = acc[i][i];
        }
    }
}

// ---------------------------------------------------------------------------
// Kernel 3: diag of matrix products without forming them.
// One warp per (b, i): d5 = <P2[i,:], P3[:,i]>, d6 = <P3[i,:], P3[:,i]>,
// d7 = <P3[i,:], P4[:,i]>.
// ---------------------------------------------------------------------------
__global__ void __launch_bounds__(256) diag_kernel(const float* __restrict__ P2,
                                                   const float* __restrict__ P3,
                                                   const float* __restrict__ P4,
                                                   float* __restrict__ out)
{
    int gw   = (blockIdx.x * blockDim.x + threadIdx.x) >> 5;
    int lane = threadIdx.x & 31;
    int b = gw >> 8;
    int i = gw & 255;
    size_t base = (size_t)b << 16;

    const float* r2 = P2 + base + (size_t)i * NN;
    const float* r3 = P3 + base + (size_t)i * NN;

    float a5 = 0.0f, a6 = 0.0f, a7 = 0.0f;
    #pragma unroll
    for (int j = lane; j < NN; j += 32) {
        float c3 = P3[base + (size_t)j * NN + i];
        float c4 = P4[base + (size_t)j * NN + i];
        float x2 = r2[j];
        float x3 = r3[j];
        a5 = fmaf(x2, c3, a5);
        a6 = fmaf(x3, c3, a6);
        a7 = fmaf(x3, c4, a7);
    }
    #pragma unroll
    for (int o = 16; o; o >>= 1) {
        a5 += __shfl_xor_sync(0xffffffffu, a5, o);
        a6 += __shfl_xor_sync(0xffffffffu, a6, o);
        a7 += __shfl_xor_sync(0xffffffffu, a7, o);
    }
    if (lane == 0) {
        size_t o = ((size_t)b * NN + i) * 8;
        out[o + 5] = a5;
        out[o + 6] = a6;
        out[o + 7] = a7;
    }
}

// ---------------------------------------------------------------------------
extern "C" void kernel_launch(void* const* d_in, const int* in_sizes, int n_in,
                              void* d_out, int out_size)
{
    const float* A = (const float*)d_in[0];
    float* out = (float*)d_out;

    float *P, *P2, *P3, *P4;
    cudaGetSymbolAddress((void**)&P,  g_P);
    cudaGetSymbolAddress((void**)&P2, g_P2);
    cudaGetSymbolAddress((void**)&P3, g_P3);
    cudaGetSymbolAddress((void**)&P4, g_P4);

    // 1) P from A (+ slots 0,1)
    prep_kernel<<<256 * 256, 256>>>(A, P, out);

    // 2) P2 = P * P (+ slot 2)
    gemm_kernel<<<dim3(4, 256, 1), 256>>>(P, P, P2, 2,
                                          P, P, P2, 2, out);

    // 3) P3 = P * P2 (+ slot 3) and P4 = P2 * P2 (+ slot 4), one launch
    gemm_kernel<<<dim3(4, 256, 2), 256>>>(P,  P2, P3, 3,
                                          P2, P2, P4, 4, out);

    // 4) slots 5,6,7 via diag-of-product dot products
    diag_kernel<<<(256 * 256 * 32) / 256, 256>>>(P2, P3, P4, out);
}

// round 3
// speedup vs baseline: 1.5390x; 1.5390x over previous
#include <cuda_runtime.h>
#include <cuda_bf16.h>
#include <mma.h>
#include <cstdint>

using namespace nvcuda;

#define NN 256
#define MATS (256LL * 256 * 256)

// scratch (static __device__ arrays: allocation-free)
__device__ __nv_bfloat16 g_Phi[MATS], g_Plo[MATS], g_PThi[MATS], g_PTlo[MATS];
__device__ __nv_bfloat16 g_P2hi[MATS], g_P2lo[MATS], g_P2Thi[MATS], g_P2Tlo[MATS];
__device__ float g_P2[MATS], g_P3[MATS], g_P4[MATS];

__device__ __forceinline__ uint32_t smem_u32(const void* p) {
    uint32_t a;
    asm("{ .reg .u64 t; cvta.to.shared.u64 t, %1; cvt.u32.u64 %0, t; }" : "=r"(a) : "l"(p));
    return a;
}
__device__ __forceinline__ void cpa16(uint32_t dst, const void* src) {
    asm volatile("cp.async.cg.shared.global [%0], [%1], 16;" :: "r"(dst), "l"(src));
}
__device__ __forceinline__ void cpa_commit() {
    asm volatile("cp.async.commit_group;" ::: "memory");
}
__device__ __forceinline__ void cpa_wait0() {
    asm volatile("cp.async.wait_group 0;" ::: "memory");
}

// ---------------------------------------------------------------------------
// prep: threshold + row-normalize, write bf16 hi/lo of P, slots 0/1
// ---------------------------------------------------------------------------
__global__ void __launch_bounds__(256) prep_kernel(const float* __restrict__ A,
                                                   __nv_bfloat16* __restrict__ Phi,
                                                   __nv_bfloat16* __restrict__ Plo,
                                                   float* __restrict__ out)
{
    int row = blockIdx.x;          // b*256 + n
    int n = row & 255;
    int t = threadIdx.x;

    float v = A[(size_t)row * NN + t];
    float a = (v > 0.3f) ? v : 0.0f;

    float s = a;
    #pragma unroll
    for (int o = 16; o; o >>= 1) s += __shfl_xor_sync(0xffffffffu, s, o);
    __shared__ float ws[8];
    if ((t & 31) == 0) ws[t >> 5] = s;
    __syncthreads();
    float deg = ws[0] + ws[1] + ws[2] + ws[3] + ws[4] + ws[5] + ws[6] + ws[7];
    float dinv = (deg > 0.0f) ? (1.0f / deg) : 0.0f;
    float p = a * dinv;

    __nv_bfloat16 h = __float2bfloat16_rn(p);
    __nv_bfloat16 l = __float2bfloat16_rn(p - __bfloat162float(h));
    size_t idx = (size_t)row * NN + t;
    Phi[idx] = h;
    Plo[idx] = l;

    if (t == n) out[(size_t)row * 8 + 1] = p;
    if (t == 0) out[(size_t)row * 8 + 0] = 1.0f;
}

// ---------------------------------------------------------------------------
// transpose bf16 hi/lo pair, per-batch 256x256 (P -> P^T)
// ---------------------------------------------------------------------------
__global__ void __launch_bounds__(256) transpose_bf(const __nv_bfloat16* __restrict__ hi,
                                                    const __nv_bfloat16* __restrict__ lo,
                                                    __nv_bfloat16* __restrict__ thi,
                                                    __nv_bfloat16* __restrict__ tlo)
{
    __shared__ __nv_bfloat16 sh[32][33], sl[32][33];
    int tile = blockIdx.x;
    int tx = (tile & 7) << 5, ty = (tile >> 3) << 5;
    size_t base = (size_t)blockIdx.y << 16;
    int t = threadIdx.x, c = t & 31, r0 = t >> 5;

    #pragma unroll
    for (int q = 0; q < 4; q++) {
        int r = r0 + q * 8;
        size_t src = base + (size_t)(ty + r) * NN + tx + c;
        sh[r][c] = hi[src];
        sl[r][c] = lo[src];
    }
    __syncthreads();
    #pragma unroll
    for (int q = 0; q < 4; q++) {
        int r = r0 + q * 8;
        size_t dst = base + (size_t)(tx + r) * NN + ty + c;
        thi[dst] = sh[c][r];
        tlo[dst] = sl[c][r];
    }
}

// ---------------------------------------------------------------------------
// convsplit: fp32 C -> bf16 hi/lo (row-major) + bf16 hi/lo transposed
// ---------------------------------------------------------------------------
__global__ void __launch_bounds__(256) convsplit_kernel(const float* __restrict__ C,
                                                        __nv_bfloat16* __restrict__ hi,
                                                        __nv_bfloat16* __restrict__ lo,
                                                        __nv_bfloat16* __restrict__ thi,
                                                        __nv_bfloat16* __restrict__ tlo)
{
    __shared__ float sf[32][33];
    int tile = blockIdx.x;
    int tx = (tile & 7) << 5, ty = (tile >> 3) << 5;
    size_t base = (size_t)blockIdx.y << 16;
    int t = threadIdx.x, c = t & 31, r0 = t >> 5;

    #pragma unroll
    for (int q = 0; q < 4; q++) {
        int r = r0 + q * 8;
        size_t src = base + (size_t)(ty + r) * NN + tx + c;
        float v = C[src];
        __nv_bfloat16 h = __float2bfloat16_rn(v);
        hi[src] = h;
        lo[src] = __float2bfloat16_rn(v - __bfloat162float(h));
        sf[r][c] = v;
    }
    __syncthreads();
    #pragma unroll
    for (int q = 0; q < 4; q++) {
        int r = r0 + q * 8;
        float v = sf[c][r];
        size_t dst = base + (size_t)(tx + r) * NN + ty + c;
        __nv_bfloat16 h = __float2bfloat16_rn(v);
        thi[dst] = h;
        tlo[dst] = __float2bfloat16_rn(v - __bfloat162float(h));
    }
}

// ---------------------------------------------------------------------------
// WMMA bf16-split GEMM: C[m,n] = sum_k X[m,k]*Y[n,k]  (Y is transposed operand)
// CTA: 256 thr / 8 warps, tile 128x128, warp tile 64x32, K-chunk 32,
// double-buffered smem via cp.async. 3 split products: AhBh + AhBl + AlBh.
// ---------------------------------------------------------------------------
#define LDS 56                              // bf16 elems per smem row (112B, conflict-free LDSM)
#define ARR_B (128 * LDS * 2)               // 14336 bytes per tile array
#define STAGE_B (4 * ARR_B)                 // Xh, Xl, Yh, Yl
#define GEMM_SMEM (2 * STAGE_B)             // 114688

__global__ void __launch_bounds__(256, 1)
gemm_wmma(const __nv_bfloat16* __restrict__ Xh0, const __nv_bfloat16* __restrict__ Xl0,
          const __nv_bfloat16* __restrict__ Yh0, const __nv_bfloat16* __restrict__ Yl0,
          float* __restrict__ C0,
          const __nv_bfloat16* __restrict__ Xh1, const __nv_bfloat16* __restrict__ Xl1,
          const __nv_bfloat16* __restrict__ Yh1, const __nv_bfloat16* __restrict__ Yl1,
          float* __restrict__ C1)
{
    const __nv_bfloat16* Xh = blockIdx.z ? Xh1 : Xh0;
    const __nv_bfloat16* Xl = blockIdx.z ? Xl1 : Xl0;
    const __nv_bfloat16* Yh = blockIdx.z ? Yh1 : Yh0;
    const __nv_bfloat16* Yl = blockIdx.z ? Yl1 : Yl0;
    float* C = blockIdx.z ? C1 : C0;

    size_t base = (size_t)blockIdx.y << 16;
    Xh += base; Xl += base; Yh += base; Yl += base; C += base;
    int tileM = (blockIdx.x >> 1) << 7;
    int tileN = (blockIdx.x & 1) << 7;

    extern __shared__ __align__(128) char sm[];
    uint32_t smb = smem_u32(sm);

    int t = threadIdx.x;
    int w = t >> 5, wm = w & 1, wn = w >> 1;   // warp tile: rows wm*64, cols wn*32
    int r = t >> 2, q = t & 3;                  // loader mapping: 64 rows x 4 uint4

    wmma::fragment<wmma::accumulator, 16, 16, 16, float> acc[4][2];
    #pragma unroll
    for (int i = 0; i < 4; i++)
        #pragma unroll
        for (int j = 0; j < 2; j++) wmma::fill_fragment(acc[i][j], 0.0f);

    // issue one K-chunk (32 cols) of all 4 tiles into stage s
    auto issue = [&](int kc, int s) {
        int k0 = kc << 5;
        uint32_t sb = smb + s * STAGE_B;
        uint32_t d;
        const __nv_bfloat16* g;
        // X hi
        g = Xh + (size_t)(tileM + r) * NN + k0 + q * 8;
        d = sb + 0 * ARR_B + r * 112 + q * 16;
        cpa16(d, g); cpa16(d + 64 * 112, g + 64 * NN);
        // X lo
        g = Xl + (size_t)(tileM + r) * NN + k0 + q * 8;
        d = sb + 1 * ARR_B + r * 112 + q * 16;
        cpa16(d, g); cpa16(d + 64 * 112, g + 64 * NN);
        // Y hi
        g = Yh + (size_t)(tileN + r) * NN + k0 + q * 8;
        d = sb + 2 * ARR_B + r * 112 + q * 16;
        cpa16(d, g); cpa16(d + 64 * 112, g + 64 * NN);
        // Y lo
        g = Yl + (size_t)(tileN + r) * NN + k0 + q * 8;
        d = sb + 3 * ARR_B + r * 112 + q * 16;
        cpa16(d, g); cpa16(d + 64 * 112, g + 64 * NN);
        cpa_commit();
    };

    issue(0, 0);

    #pragma unroll 1
    for (int kc = 0; kc < 8; kc++) {
        int s = kc & 1;
        cpa_wait0();
        __syncthreads();
        if (kc < 7) issue(kc + 1, s ^ 1);

        const __nv_bfloat16* bXh = (const __nv_bfloat16*)(sm + s * STAGE_B + 0 * ARR_B);
        const __nv_bfloat16* bXl = (const __nv_bfloat16*)(sm + s * STAGE_B + 1 * ARR_B);
        const __nv_bfloat16* bYh = (const __nv_bfloat16*)(sm + s * STAGE_B + 2 * ARR_B);
        const __nv_bfloat16* bYl = (const __nv_bfloat16*)(sm + s * STAGE_B + 3 * ARR_B);

        #pragma unroll
        for (int kk = 0; kk < 2; kk++) {
            int ks = kk * 16;
            wmma::fragment<wmma::matrix_a, 16, 16, 16, __nv_bfloat16, wmma::row_major> ah[4], al[4];
            wmma::fragment<wmma::matrix_b, 16, 16, 16, __nv_bfloat16, wmma::col_major> bh[2], bl[2];
            #pragma unroll
            for (int i = 0; i < 4; i++) {
                wmma::load_matrix_sync(ah[i], bXh + (wm * 64 + i * 16) * LDS + ks, LDS);
                wmma::load_matrix_sync(al[i], bXl + (wm * 64 + i * 16) * LDS + ks, LDS);
            }
            #pragma unroll
            for (int j = 0; j < 2; j++) {
                wmma::load_matrix_sync(bh[j], bYh + (wn * 32 + j * 16) * LDS + ks, LDS);
                wmma::load_matrix_sync(bl[j], bYl + (wn * 32 + j * 16) * LDS + ks, LDS);
            }
            #pragma unroll
            for (int i = 0; i < 4; i++)
                #pragma unroll
                for (int j = 0; j < 2; j++) {
                    wmma::mma_sync(acc[i][j], ah[i], bh[j], acc[i][j]);
                    wmma::mma_sync(acc[i][j], ah[i], bl[j], acc[i][j]);
                    wmma::mma_sync(acc[i][j], al[i], bh[j], acc[i][j]);
                }
        }
        __syncthreads();
    }

    #pragma unroll
    for (int i = 0; i < 4; i++)
        #pragma unroll
        for (int j = 0; j < 2; j++) {
            float* cp = C + (size_t)(tileM + wm * 64 + i * 16) * NN + tileN + wn * 32 + j * 16;
            wmma::store_matrix_sync(cp, acc[i][j], NN, wmma::mem_row_major);
        }
}

// ---------------------------------------------------------------------------
// diag_extract: slots 2,3,4 from diagonals of P2,P3,P4
// ---------------------------------------------------------------------------
__global__ void __launch_bounds__(256) diag_extract(const float* __restrict__ P2,
                                                    const float* __restrict__ P3,
                                                    const float* __restrict__ P4,
                                                    float* __restrict__ out)
{
    int b = blockIdx.x, i = threadIdx.x;
    size_t d = ((size_t)b << 16) + (size_t)i * (NN + 1);
    size_t o = ((size_t)b * NN + i) * 8;
    out[o + 2] = P2[d];
    out[o + 3] = P3[d];
    out[o + 4] = P4[d];
}

// ---------------------------------------------------------------------------
// diag3: slots 5,6,7 with smem-transposed (coalesced) column reads.
// d5 = <P2[i,:], P3[:,i]>, d6 = <P3[i,:], P3[:,i]>, d7 = <P3[i,:], P4[:,i]>
// ---------------------------------------------------------------------------
__global__ void __launch_bounds__(256) diag3_kernel(const float* __restrict__ P2,
                                                    const float* __restrict__ P3,
                                                    const float* __restrict__ P4,
                                                    float* __restrict__ out)
{
    __shared__ float c3[32][33], c4[32][33];
    int b = blockIdx.x >> 3;
    int i0 = (blockIdx.x & 7) << 5;
    size_t base = (size_t)b << 16;
    int t = threadIdx.x;
    int il = t >> 3, jq = t & 7;
    int lc = t & 31, lr = t >> 5;

    const float* r2 = P2 + base + (size_t)(i0 + il) * NN;
    const float* r3 = P3 + base + (size_t)(i0 + il) * NN;

    float a5 = 0.f, a6 = 0.f, a7 = 0.f;
    #pragma unroll 1
    for (int jt = 0; jt < 8; jt++) {
        int j0 = jt << 5;
        #pragma unroll
        for (int qq = 0; qq < 4; qq++) {
            int jl = lr + qq * 8;
            size_t src = base + (size_t)(j0 + jl) * NN + i0 + lc;
            c3[jl][lc] = P3[src];
            c4[jl][lc] = P4[src];
        }
        __syncthreads();
        float4 x2 = *(const float4*)(r2 + j0 + jq * 4);
        float4 x3 = *(const float4*)(r3 + j0 + jq * 4);
        int jb = jq * 4;
        a5 = fmaf(x2.x, c3[jb+0][il], a5); a5 = fmaf(x2.y, c3[jb+1][il], a5);
        a5 = fmaf(x2.z, c3[jb+2][il], a5); a5 = fmaf(x2.w, c3[jb+3][il], a5);
        a6 = fmaf(x3.x, c3[jb+0][il], a6); a6 = fmaf(x3.y, c3[jb+1][il], a6);
        a6 = fmaf(x3.z, c3[jb+2][il], a6); a6 = fmaf(x3.w, c3[jb+3][il], a6);
        a7 = fmaf(x3.x, c4[jb+0][il], a7); a7 = fmaf(x3.y, c4[jb+1][il], a7);
        a7 = fmaf(x3.z, c4[jb+2][il], a7); a7 = fmaf(x3.w, c4[jb+3][il], a7);
        __syncthreads();
    }
    #pragma unroll
    for (int o = 4; o; o >>= 1) {
        a5 += __shfl_down_sync(0xffffffffu, a5, o);
        a6 += __shfl_down_sync(0xffffffffu, a6, o);
        a7 += __shfl_down_sync(0xffffffffu, a7, o);
    }
    if (jq == 0) {
        size_t o = ((size_t)b * NN + i0 + il) * 8;
        out[o + 5] = a5;
        out[o + 6] = a6;
        out[o + 7] = a7;
    }
}

// ---------------------------------------------------------------------------
extern "C" void kernel_launch(void* const* d_in, const int* in_sizes, int n_in,
                              void* d_out, int out_size)
{
    const float* A = (const float*)d_in[0];
    float* out = (float*)d_out;

    __nv_bfloat16 *Phi, *Plo, *PThi, *PTlo, *P2hi, *P2lo, *P2Thi, *P2Tlo;
    float *P2, *P3, *P4;
    cudaGetSymbolAddress((void**)&Phi,  g_Phi);
    cudaGetSymbolAddress((void**)&Plo,  g_Plo);
    cudaGetSymbolAddress((void**)&PThi, g_PThi);
    cudaGetSymbolAddress((void**)&PTlo, g_PTlo);
    cudaGetSymbolAddress((void**)&P2hi, g_P2hi);
    cudaGetSymbolAddress((void**)&P2lo, g_P2lo);
    cudaGetSymbolAddress((void**)&P2Thi, g_P2Thi);
    cudaGetSymbolAddress((void**)&P2Tlo, g_P2Tlo);
    cudaGetSymbolAddress((void**)&P2, g_P2);
    cudaGetSymbolAddress((void**)&P3, g_P3);
    cudaGetSymbolAddress((void**)&P4, g_P4);

    cudaFuncSetAttribute(gemm_wmma, cudaFuncAttributeMaxDynamicSharedMemorySize, GEMM_SMEM);

    // 1) P (bf16 hi/lo) + slots 0,1
    prep_kernel<<<256 * 256, 256>>>(A, Phi, Plo, out);
    // 2) P^T (bf16 hi/lo)
    transpose_bf<<<dim3(64, 256), 256>>>(Phi, Plo, PThi, PTlo);
    // 3) P2 = P * P^T-form  (fp32)
    gemm_wmma<<<dim3(4, 256, 1), 256, GEMM_SMEM>>>(
        Phi, Plo, PThi, PTlo, P2,
        Phi, Plo, PThi, PTlo, P2);
    // 4) P2 -> bf16 hi/lo + transposed hi/lo
    convsplit_kernel<<<dim3(64, 256), 256>>>(P2, P2hi, P2lo, P2Thi, P2Tlo);
    // 5) P3 = P*P2, P4 = P2*P2 (dual launch, fp32)
    gemm_wmma<<<dim3(4, 256, 2), 256, GEMM_SMEM>>>(
        Phi,  Plo,  P2Thi, P2Tlo, P3,
        P2hi, P2lo, P2Thi, P2Tlo, P4);
    // 6) slots 2,3,4
    diag_extract<<<256, 256>>>(P2, P3, P4, out);
    // 7) slots 5,6,7
    diag3_kernel<<<256 * 8, 256>>>(P2, P3, P4, out);
}

// round 4
// speedup vs baseline: 1.9529x; 1.2689x over previous
#include <cuda_runtime.h>
#include <cuda_bf16.h>
#include <mma.h>
#include <cstdint>

using namespace nvcuda;

#define NN 256
#define MATS (256LL * 256 * 256)

// scratch (static __device__ arrays: allocation-free)
__device__ __nv_bfloat16 g_Phi[MATS], g_Plo[MATS];
__device__ __nv_bfloat16 g_P2hi[MATS], g_P2lo[MATS];
__device__ float g_P2[MATS], g_P3[MATS], g_P4[MATS];

__device__ __forceinline__ uint32_t smem_u32(const void* p) {
    uint32_t a;
    asm("{ .reg .u64 t; cvta.to.shared.u64 t, %1; cvt.u32.u64 %0, t; }" : "=r"(a) : "l"(p));
    return a;
}
__device__ __forceinline__ void cpa16(uint32_t dst, const void* src) {
    asm volatile("cp.async.cg.shared.global [%0], [%1], 16;" :: "r"(dst), "l"(src));
}
__device__ __forceinline__ void cpa_commit() {
    asm volatile("cp.async.commit_group;" ::: "memory");
}
__device__ __forceinline__ void cpa_wait0() {
    asm volatile("cp.async.wait_group 0;" ::: "memory");
}

// ---------------------------------------------------------------------------
// prep: threshold + row-normalize, write bf16 hi/lo of P, slots 0/1
// ---------------------------------------------------------------------------
__global__ void __launch_bounds__(256) prep_kernel(const float* __restrict__ A,
                                                   __nv_bfloat16* __restrict__ Phi,
                                                   __nv_bfloat16* __restrict__ Plo,
                                                   float* __restrict__ out)
{
    int row = blockIdx.x;          // b*256 + n
    int n = row & 255;
    int t = threadIdx.x;

    float v = A[(size_t)row * NN + t];
    float a = (v > 0.3f) ? v : 0.0f;

    float s = a;
    #pragma unroll
    for (int o = 16; o; o >>= 1) s += __shfl_xor_sync(0xffffffffu, s, o);
    __shared__ float ws[8];
    if ((t & 31) == 0) ws[t >> 5] = s;
    __syncthreads();
    float deg = ws[0] + ws[1] + ws[2] + ws[3] + ws[4] + ws[5] + ws[6] + ws[7];
    float dinv = (deg > 0.0f) ? (1.0f / deg) : 0.0f;
    float p = a * dinv;

    __nv_bfloat16 h = __float2bfloat16_rn(p);
    __nv_bfloat16 l = __float2bfloat16_rn(p - __bfloat162float(h));
    size_t idx = (size_t)row * NN + t;
    Phi[idx] = h;
    Plo[idx] = l;

    if (t == n) out[(size_t)row * 8 + 1] = p;
    if (t == 0) out[(size_t)row * 8 + 0] = 1.0f;
}

// ---------------------------------------------------------------------------
// WMMA bf16-split GEMM: C = X * Y, both row-major ([M,K] and [K,N]).
// CTA: 256 thr / 8 warps, tile 128x128, warp tile 64x32, K-chunk 32,
// double-buffered smem via cp.async. 3 split products: XhYh + XhYl + XlYh.
// If Chi != nullptr: epilogue also emits bf16 hi/lo split of C (fused, via
// smem staging).
// ---------------------------------------------------------------------------
#define XLD 40                               // X smem ld (elems): 32 + 8 pad (80B rows)
#define YLD 136                              // Y smem ld (elems): 128 + 8 pad (272B rows)
#define XARR_B (128 * XLD * 2)               // 10240
#define YARR_B (32 * YLD * 2)                // 8704
#define OFF_XL XARR_B                        // 10240
#define OFF_YH (2 * XARR_B)                  // 20480
#define OFF_YL (2 * XARR_B + YARR_B)         // 29184
#define STAGE_B (2 * XARR_B + 2 * YARR_B)    // 37888
#define GEMM_SMEM (2 * STAGE_B)              // 75776  (epilogue staging 128*132*4=67584 fits)

__global__ void __launch_bounds__(256, 2)
gemm_wmma(const __nv_bfloat16* __restrict__ Xh0, const __nv_bfloat16* __restrict__ Xl0,
          const __nv_bfloat16* __restrict__ Yh0, const __nv_bfloat16* __restrict__ Yl0,
          float* __restrict__ C0, __nv_bfloat16* Chi0, __nv_bfloat16* Clo0,
          const __nv_bfloat16* __restrict__ Xh1, const __nv_bfloat16* __restrict__ Xl1,
          const __nv_bfloat16* __restrict__ Yh1, const __nv_bfloat16* __restrict__ Yl1,
          float* __restrict__ C1, __nv_bfloat16* Chi1, __nv_bfloat16* Clo1)
{
    const __nv_bfloat16* Xh = blockIdx.z ? Xh1 : Xh0;
    const __nv_bfloat16* Xl = blockIdx.z ? Xl1 : Xl0;
    const __nv_bfloat16* Yh = blockIdx.z ? Yh1 : Yh0;
    const __nv_bfloat16* Yl = blockIdx.z ? Yl1 : Yl0;
    float* C = blockIdx.z ? C1 : C0;
    __nv_bfloat16* Chi = blockIdx.z ? Chi1 : Chi0;
    __nv_bfloat16* Clo = blockIdx.z ? Clo1 : Clo0;

    size_t base = (size_t)blockIdx.y << 16;
    Xh += base; Xl += base; Yh += base; Yl += base; C += base;
    if (Chi) { Chi += base; Clo += base; }
    int tileM = (blockIdx.x >> 1) << 7;
    int tileN = (blockIdx.x & 1) << 7;

    extern __shared__ __align__(128) char sm[];
    uint32_t smb = smem_u32(sm);

    int t = threadIdx.x;
    int w = t >> 5, wm = w & 1, wn = w >> 1;   // warp tile: rows wm*64, cols wn*32

    // loader index splits
    int xr = t >> 1, xq = t & 1;   // X: 128 rows x 2 halves of 64B? -> see below
    int yr = t >> 4, yq = t & 15;  // Y: 32 rows x 16 quads (256B rows)

    wmma::fragment<wmma::accumulator, 16, 16, 16, float> acc[4][2];
    #pragma unroll
    for (int i = 0; i < 4; i++)
        #pragma unroll
        for (int j = 0; j < 2; j++) wmma::fill_fragment(acc[i][j], 0.0f);

    // issue one K-chunk (32 cols of X / 32 rows of Y) into stage s
    auto issue = [&](int kc, int s) {
        int k0 = kc << 5;
        uint32_t sb = smb + s * STAGE_B;
        // X tiles: 128 rows x 64B each (32 bf16); 2 x 16B per thread per array
        {
            const __nv_bfloat16* gh = Xh + (size_t)(tileM + xr) * NN + k0 + xq * 16;
            const __nv_bfloat16* gl = Xl + (size_t)(tileM + xr) * NN + k0 + xq * 16;
            uint32_t d = sb + xr * (XLD * 2) + xq * 32;
            cpa16(d, gh);               cpa16(d + 16, gh + 8);
            cpa16(d + OFF_XL, gl);      cpa16(d + OFF_XL + 16, gl + 8);
        }
        // Y tiles: 32 rows x 256B each; 1 x 16B per thread per array x 2 halves
        {
            const __nv_bfloat16* gh = Yh + (size_t)(k0 + yr) * NN + tileN + yq * 8;
            const __nv_bfloat16* gl = Yl + (size_t)(k0 + yr) * NN + tileN + yq * 8;
            uint32_t d = sb + OFF_YH + yr * (YLD * 2) + yq * 16;
            cpa16(d, gh);               cpa16(d + 16 * (YLD * 2), gh + 16 * NN);
            cpa16(d + YARR_B, gl);      cpa16(d + YARR_B + 16 * (YLD * 2), gl + 16 * NN);
        }
        cpa_commit();
    };

    issue(0, 0);

    #pragma unroll 1
    for (int kc = 0; kc < 8; kc++) {
        int s = kc & 1;
        cpa_wait0();
        __syncthreads();
        if (kc < 7) issue(kc + 1, s ^ 1);

        const __nv_bfloat16* bXh = (const __nv_bfloat16*)(sm + s * STAGE_B);
        const __nv_bfloat16* bXl = (const __nv_bfloat16*)(sm + s * STAGE_B + OFF_XL);
        const __nv_bfloat16* bYh = (const __nv_bfloat16*)(sm + s * STAGE_B + OFF_YH);
        const __nv_bfloat16* bYl = (const __nv_bfloat16*)(sm + s * STAGE_B + OFF_YL);

        #pragma unroll
        for (int kk = 0; kk < 2; kk++) {
            int ks = kk * 16;
            wmma::fragment<wmma::matrix_a, 16, 16, 16, __nv_bfloat16, wmma::row_major> ah[4], al[4];
            wmma::fragment<wmma::matrix_b, 16, 16, 16, __nv_bfloat16, wmma::row_major> bh[2], bl[2];
            #pragma unroll
            for (int i = 0; i < 4; i++) {
                wmma::load_matrix_sync(ah[i], bXh + (wm * 64 + i * 16) * XLD + ks, XLD);
                wmma::load_matrix_sync(al[i], bXl + (wm * 64 + i * 16) * XLD + ks, XLD);
            }
            #pragma unroll
            for (int j = 0; j < 2; j++) {
                wmma::load_matrix_sync(bh[j], bYh + ks * YLD + wn * 32 + j * 16, YLD);
                wmma::load_matrix_sync(bl[j], bYl + ks * YLD + wn * 32 + j * 16, YLD);
            }
            #pragma unroll
            for (int i = 0; i < 4; i++)
                #pragma unroll
                for (int j = 0; j < 2; j++) {
                    wmma::mma_sync(acc[i][j], ah[i], bh[j], acc[i][j]);
                    wmma::mma_sync(acc[i][j], ah[i], bl[j], acc[i][j]);
                    wmma::mma_sync(acc[i][j], al[i], bh[j], acc[i][j]);
                }
        }
        __syncthreads();
    }

    if (!Chi) {
        // plain fp32 epilogue
        #pragma unroll
        for (int i = 0; i < 4; i++)
            #pragma unroll
            for (int j = 0; j < 2; j++) {
                float* cp = C + (size_t)(tileM + wm * 64 + i * 16) * NN + tileN + wn * 32 + j * 16;
                wmma::store_matrix_sync(cp, acc[i][j], NN, wmma::mem_row_major);
            }
    } else {
        // fused split epilogue via smem staging (128x132 fp32)
        float* cs = (float*)sm;
        #pragma unroll
        for (int i = 0; i < 4; i++)
            #pragma unroll
            for (int j = 0; j < 2; j++)
                wmma::store_matrix_sync(cs + (wm * 64 + i * 16) * 132 + wn * 32 + j * 16,
                                        acc[i][j], 132, wmma::mem_row_major);
        __syncthreads();
        #pragma unroll
        for (int it = 0; it < 8; it++) {
            int idx = t + it * 256;          // 2048 chunks of 8 floats
            int r = idx >> 4;                // 128 rows
            int c = (idx & 15) << 3;         // 16 chunks x 8 floats
            const float* sp = cs + r * 132 + c;
            float4 v0 = *(const float4*)(sp);
            float4 v1 = *(const float4*)(sp + 4);
            float* cp = C + (size_t)(tileM + r) * NN + tileN + c;
            *(float4*)cp = v0;
            *(float4*)(cp + 4) = v1;

            float f[8] = {v0.x, v0.y, v0.z, v0.w, v1.x, v1.y, v1.z, v1.w};
            uint32_t hp[4], lp[4];
            #pragma unroll
            for (int q = 0; q < 4; q++) {
                __nv_bfloat16 h0 = __float2bfloat16_rn(f[2*q]);
                __nv_bfloat16 h1 = __float2bfloat16_rn(f[2*q+1]);
                __nv_bfloat162 hh; hh.x = h0; hh.y = h1;
                hp[q] = *(uint32_t*)&hh;
                __nv_bfloat162 ll;
                ll.x = __float2bfloat16_rn(f[2*q]   - __bfloat162float(h0));
                ll.y = __float2bfloat16_rn(f[2*q+1] - __bfloat162float(h1));
                lp[q] = *(uint32_t*)&ll;
            }
            *(uint4*)(Chi + (size_t)(tileM + r) * NN + tileN + c) = make_uint4(hp[0], hp[1], hp[2], hp[3]);
            *(uint4*)(Clo + (size_t)(tileM + r) * NN + tileN + c) = make_uint4(lp[0], lp[1], lp[2], lp[3]);
        }
    }
}

// ---------------------------------------------------------------------------
// diag_extract: slots 2,3,4 from diagonals of P2,P3,P4
// ---------------------------------------------------------------------------
__global__ void __launch_bounds__(256) diag_extract(const float* __restrict__ P2,
                                                    const float* __restrict__ P3,
                                                    const float* __restrict__ P4,
                                                    float* __restrict__ out)
{
    int b = blockIdx.x, i = threadIdx.x;
    size_t d = ((size_t)b << 16) + (size_t)i * (NN + 1);
    size_t o = ((size_t)b * NN + i) * 8;
    out[o + 2] = P2[d];
    out[o + 3] = P3[d];
    out[o + 4] = P4[d];
}

// ---------------------------------------------------------------------------
// diag3: slots 5,6,7 with smem-transposed (coalesced) column reads.
// d5 = <P2[i,:], P3[:,i]>, d6 = <P3[i,:], P3[:,i]>, d7 = <P3[i,:], P4[:,i]>
// ---------------------------------------------------------------------------
__global__ void __launch_bounds__(256) diag3_kernel(const float* __restrict__ P2,
                                                    const float* __restrict__ P3,
                                                    const float* __restrict__ P4,
                                                    float* __restrict__ out)
{
    __shared__ float c3[32][33], c4[32][33];
    int b = blockIdx.x >> 3;
    int i0 = (blockIdx.x & 7) << 5;
    size_t base = (size_t)b << 16;
    int t = threadIdx.x;
    int il = t >> 3, jq = t & 7;
    int lc = t & 31, lr = t >> 5;

    const float* r2 = P2 + base + (size_t)(i0 + il) * NN;
    const float* r3 = P3 + base + (size_t)(i0 + il) * NN;

    float a5 = 0.f, a6 = 0.f, a7 = 0.f;
    #pragma unroll 1
    for (int jt = 0; jt < 8; jt++) {
        int j0 = jt << 5;
        #pragma unroll
        for (int qq = 0; qq < 4; qq++) {
            int jl = lr + qq * 8;
            size_t src = base + (size_t)(j0 + jl) * NN + i0 + lc;
            c3[jl][lc] = P3[src];
            c4[jl][lc] = P4[src];
        }
        __syncthreads();
        float4 x2 = *(const float4*)(r2 + j0 + jq * 4);
        float4 x3 = *(const float4*)(r3 + j0 + jq * 4);
        int jb = jq * 4;
        a5 = fmaf(x2.x, c3[jb+0][il], a5); a5 = fmaf(x2.y, c3[jb+1][il], a5);
        a5 = fmaf(x2.z, c3[jb+2][il], a5); a5 = fmaf(x2.w, c3[jb+3][il], a5);
        a6 = fmaf(x3.x, c3[jb+0][il], a6); a6 = fmaf(x3.y, c3[jb+1][il], a6);
        a6 = fmaf(x3.z, c3[jb+2][il], a6); a6 = fmaf(x3.w, c3[jb+3][il], a6);
        a7 = fmaf(x3.x, c4[jb+0][il], a7); a7 = fmaf(x3.y, c4[jb+1][il], a7);
        a7 = fmaf(x3.z, c4[jb+2][il], a7); a7 = fmaf(x3.w, c4[jb+3][il], a7);
        __syncthreads();
    }
    #pragma unroll
    for (int o = 4; o; o >>= 1) {
        a5 += __shfl_down_sync(0xffffffffu, a5, o);
        a6 += __shfl_down_sync(0xffffffffu, a6, o);
        a7 += __shfl_down_sync(0xffffffffu, a7, o);
    }
    if (jq == 0) {
        size_t o = ((size_t)b * NN + i0 + il) * 8;
        out[o + 5] = a5;
        out[o + 6] = a6;
        out[o + 7] = a7;
    }
}

// ---------------------------------------------------------------------------
extern "C" void kernel_launch(void* const* d_in, const int* in_sizes, int n_in,
                              void* d_out, int out_size)
{
    const float* A = (const float*)d_in[0];
    float* out = (float*)d_out;

    __nv_bfloat16 *Phi, *Plo, *P2hi, *P2lo;
    float *P2, *P3, *P4;
    cudaGetSymbolAddress((void**)&Phi,  g_Phi);
    cudaGetSymbolAddress((void**)&Plo,  g_Plo);
    cudaGetSymbolAddress((void**)&P2hi, g_P2hi);
    cudaGetSymbolAddress((void**)&P2lo, g_P2lo);
    cudaGetSymbolAddress((void**)&P2, g_P2);
    cudaGetSymbolAddress((void**)&P3, g_P3);
    cudaGetSymbolAddress((void**)&P4, g_P4);

    cudaFuncSetAttribute(gemm_wmma, cudaFuncAttributeMaxDynamicSharedMemorySize, GEMM_SMEM);

    // 1) P (bf16 hi/lo) + slots 0,1
    prep_kernel<<<256 * 256, 256>>>(A, Phi, Plo, out);
    // 2) P2 = P * P  (fp32 + fused bf16 hi/lo split)
    gemm_wmma<<<dim3(4, 256, 1), 256, GEMM_SMEM>>>(
        Phi, Plo, Phi, Plo, P2, P2hi, P2lo,
        Phi, Plo, Phi, Plo, P2, P2hi, P2lo);
    // 3) P3 = P*P2, P4 = P2*P2 (dual launch, fp32 only)
    gemm_wmma<<<dim3(4, 256, 2), 256, GEMM_SMEM>>>(
        Phi,  Plo,  P2hi, P2lo, P3, nullptr, nullptr,
        P2hi, P2lo, P2hi, P2lo, P4, nullptr, nullptr);
    // 4) slots 2,3,4
    diag_extract<<<256, 256>>>(P2, P3, P4, out);
    // 5) slots 5,6,7
    diag3_kernel<<<256 * 8, 256>>>(P2, P3, P4, out);
}